// round 2
// baseline (speedup 1.0000x reference)
#include <cuda_runtime.h>
#include <cuda_bf16.h>
#include <cstdint>

#define SQRT2F 1.41421356237309515f

// ---------------- scratch (allocation-free: __device__ globals) ----------------
__device__ float g_style[16 * 512];   // style[b,i]
__device__ float g_demod[16 * 512];   // demod[b,o]
__device__ float g_wsq[512 * 512];    // sum_tap conv_weight[o,i,tap]^2

// ---------------- helpers ----------------
__device__ __forceinline__ float f2tf32(float f) {
    unsigned r;
    asm("cvt.rna.tf32.f32 %0, %1;" : "=r"(r) : "f"(f));
    return __uint_as_float(r);
}

__device__ __forceinline__ void mma_tf32(float d[4],
                                         float a0, float a1, float a2, float a3,
                                         float b0, float b1) {
    asm volatile(
        "mma.sync.aligned.m16n8k8.row.col.f32.tf32.tf32.f32 "
        "{%0,%1,%2,%3}, {%4,%5,%6,%7}, {%8,%9}, {%0,%1,%2,%3};"
        : "+f"(d[0]), "+f"(d[1]), "+f"(d[2]), "+f"(d[3])
        : "r"(__float_as_uint(a0)), "r"(__float_as_uint(a1)),
          "r"(__float_as_uint(a2)), "r"(__float_as_uint(a3)),
          "r"(__float_as_uint(b0)), "r"(__float_as_uint(b1)));
}

__device__ __forceinline__ float lrelu2(float v) {
    return (v > 0.0f ? v : 0.2f * v) * SQRT2F;
}

// ---------------- small kernels (fp32 exact) ----------------
// style[b,i] = lrelu(latent[b,:] . aw[i,:] * (1/sqrt(512)) + ab[i], 0.2) * sqrt(2)
__global__ void style_kernel(const float* __restrict__ latent,
                             const float* __restrict__ aw,
                             const float* __restrict__ ab) {
    int b = blockIdx.x;
    int tid = threadIdx.x, lane = tid & 31, warp = tid >> 5;
    __shared__ float lat[512];
    lat[tid] = latent[b * 512 + tid];
    __syncthreads();
    const float wmul = rsqrtf(512.0f);
    for (int n = 0; n < 32; n++) {
        int i = warp * 32 + n;
        const float* wr = aw + (size_t)i * 512;
        float p = 0.0f;
        #pragma unroll 4
        for (int k = lane; k < 512; k += 32) p += wr[k] * lat[k];
        #pragma unroll
        for (int off = 16; off; off >>= 1) p += __shfl_xor_sync(0xFFFFFFFFu, p, off);
        if (lane == 0) {
            float s = p * wmul + ab[i];
            g_style[b * 512 + i] = lrelu2(s);
        }
    }
}

// wsq[o,i] = sum_{tap} conv_weight[o,i,tap]^2
__global__ void wsq_kernel(const float* __restrict__ cw) {
    int o = blockIdx.x, i = threadIdx.x;
    const float* p = cw + (size_t)o * 4608 + (size_t)i * 9;
    float s = 0.0f;
    #pragma unroll
    for (int t = 0; t < 9; t++) s += p[t] * p[t];
    g_wsq[o * 512 + i] = s;
}

// demod[b,o] = rsqrt(sum_i wsq[o,i]*style[b,i]^2 + 1e-8)
__global__ void demod_kernel() {
    int b = blockIdx.x;
    int tid = threadIdx.x, lane = tid & 31, warp = tid >> 5;
    __shared__ float s2[512];
    float st = g_style[b * 512 + tid];
    s2[tid] = st * st;
    __syncthreads();
    for (int n = 0; n < 32; n++) {
        int o = warp * 32 + n;
        const float* wr = g_wsq + (size_t)o * 512;
        float p = 0.0f;
        #pragma unroll 4
        for (int k = lane; k < 512; k += 32) p += wr[k] * s2[k];
        #pragma unroll
        for (int off = 16; off; off >>= 1) p += __shfl_xor_sync(0xFFFFFFFFu, p, off);
        if (lane == 0) g_demod[b * 512 + o] = rsqrtf(p + 1e-8f);
    }
}

// ---------------- main conv: implicit GEMM, tf32 mma.sync ----------------
// CTA tile: 128 cout x 128 pixels (2 image rows). K loop: cin chunks of 8, 9 taps inner.
// 8 warps (2 m x 4 n), warp tile 64x32, m16n8k8 tf32 fragments.
#define BM 128
#define BN 128
#define KC 8
#define XPAD 66   // 4*66 = 264 -> k-stride ≡ 8 (mod 32): conflict-free B loads

__global__ __launch_bounds__(256, 2)
void conv_kernel(const float* __restrict__ x, const float* __restrict__ noise,
                 const float* __restrict__ cw, const float* __restrict__ nw_p,
                 const float* __restrict__ bias, float* __restrict__ out) {
    __shared__ float Ws[9][BM][KC];     // [tap][m][k]  36864 B
    __shared__ float Xs[KC][4][XPAD];   // [k][row][col] 8448 B  (col 0 == w=-1)

    const int b  = blockIdx.z;
    const int o0 = blockIdx.y * BM;
    const int p0 = blockIdx.x * BN;
    const int h0 = p0 >> 6;                    // first of 2 output rows
    const int tid = threadIdx.x;
    const int lane = tid & 31, warp = tid >> 5;
    const int wm = (warp >> 2) * 64;           // warp m offset: 0 or 64
    const int wn = (warp & 3) * 32;            // warp n offset: 0..96
    const int g = lane >> 2, t = lane & 3;     // groupID, threadID_in_group

    const float nw = *nw_p;
    const float* xb  = x + (size_t)b * 512 * 4096;
    const float* nzb = noise + (size_t)b * 4096;
    const float* stb = g_style + b * 512;

    float d[4][4][4];
    #pragma unroll
    for (int mi = 0; mi < 4; mi++)
        #pragma unroll
        for (int nf = 0; nf < 4; nf++)
            #pragma unroll
            for (int j = 0; j < 4; j++) d[mi][nf][j] = 0.0f;

    for (int c0 = 0; c0 < 512; c0 += KC) {
        // ---- load weight tile (tf32-rounded at store) ----
        #pragma unroll 4
        for (int idx = tid; idx < 9 * BM * KC; idx += 256) {
            int m = idx / (9 * KC);
            int r = idx - m * (9 * KC);
            int k = r / 9, tap = r - k * 9;
            float v = cw[(size_t)(o0 + m) * 4608 + (size_t)(c0 + k) * 9 + tap];
            Ws[tap][m][k] = f2tf32(v);
        }
        // ---- load input tile: rows h0-1..h0+2, cols -1..64, modulated ----
        #pragma unroll 4
        for (int idx = tid; idx < KC * 4 * XPAD; idx += 256) {
            int ci = idx / (4 * XPAD);
            int r  = (idx / XPAD) & 3;
            int c  = idx - (idx / XPAD) * XPAD;
            int h = h0 - 1 + r;
            int w = c - 1;
            float v = 0.0f;
            if ((unsigned)h < 64u && (unsigned)w < 64u) {
                int ch = c0 + ci;
                v = (xb[(size_t)ch * 4096 + h * 64 + w] + nw * nzb[h * 64 + w]) * stb[ch];
                v = f2tf32(v);
            }
            Xs[ci][r][c] = v;
        }
        __syncthreads();

        #pragma unroll
        for (int tap = 0; tap < 9; tap++) {
            const int dy = tap / 3, dx = tap - dy * 3;
            // A fragments: Ws[tap][wm + mi*16 + g(+8)][t(+4)]
            float a[4][4];
            #pragma unroll
            for (int mi = 0; mi < 4; mi++) {
                int row = wm + mi * 16 + g;
                a[mi][0] = Ws[tap][row][t];
                a[mi][1] = Ws[tap][row + 8][t];
                a[mi][2] = Ws[tap][row][t + 4];
                a[mi][3] = Ws[tap][row + 8][t + 4];
            }
            #pragma unroll
            for (int nf = 0; nf < 4; nf++) {
                int nb2  = wn + nf * 8;
                int half = nb2 >> 6;                 // which of the 2 output rows
                int col  = (nb2 & 63) + g + dx;      // Xs col (0 == w=-1)
                int row  = half + dy;                // input row in [0,4)
                float b0 = Xs[t][row][col];
                float b1 = Xs[t + 4][row][col];
                #pragma unroll
                for (int mi = 0; mi < 4; mi++)
                    mma_tf32(d[mi][nf], a[mi][0], a[mi][1], a[mi][2], a[mi][3], b0, b1);
            }
        }
        __syncthreads();
    }

    // ---- epilogue: demod, bias, leaky-relu*sqrt2, direct global store ----
    const float* dm = g_demod + b * 512;
    #pragma unroll
    for (int mi = 0; mi < 4; mi++) {
        int o = o0 + wm + mi * 16 + g;
        float dem0 = dm[o],     bv0 = bias[o];
        float dem1 = dm[o + 8], bv1 = bias[o + 8];
        float* r0 = out + ((size_t)b * 512 + o) * 4096 + p0 + wn;
        float* r1 = r0 + (size_t)8 * 4096;
        #pragma unroll
        for (int nf = 0; nf < 4; nf++) {
            int col = nf * 8 + 2 * t;
            float2 v0, v1;
            v0.x = lrelu2(d[mi][nf][0] * dem0 + bv0);
            v0.y = lrelu2(d[mi][nf][1] * dem0 + bv0);
            v1.x = lrelu2(d[mi][nf][2] * dem1 + bv1);
            v1.y = lrelu2(d[mi][nf][3] * dem1 + bv1);
            *reinterpret_cast<float2*>(r0 + col) = v0;
            *reinterpret_cast<float2*>(r1 + col) = v1;
        }
    }
}

// ---------------- launch ----------------
extern "C" void kernel_launch(void* const* d_in, const int* in_sizes, int n_in,
                              void* d_out, int out_size) {
    const float* x      = (const float*)d_in[0];
    const float* latent = (const float*)d_in[1];
    const float* noise  = (const float*)d_in[2];
    const float* aw     = (const float*)d_in[3];
    const float* ab     = (const float*)d_in[4];
    const float* cw     = (const float*)d_in[5];
    const float* nw     = (const float*)d_in[6];
    const float* bias   = (const float*)d_in[7];
    float* out = (float*)d_out;

    style_kernel<<<16, 512>>>(latent, aw, ab);
    wsq_kernel<<<512, 512>>>(cw);
    demod_kernel<<<16, 512>>>();
    conv_kernel<<<dim3(32, 4, 16), 256>>>(x, noise, cw, nw, bias, out);
}

// round 3
// speedup vs baseline: 2.2152x; 2.2152x over previous
#include <cuda_runtime.h>
#include <cuda_bf16.h>
#include <cstdint>

#define SQRT2F 1.41421356237309515f

// ---------------- scratch (allocation-free: __device__ globals) ----------------
__device__ float g_style[16 * 512];                 // style[b,i]
__device__ float g_demod[16 * 512];                 // demod[b,o]
__device__ float g_wsq[512 * 512];                  // sum_tap w[o,i,tap]^2
__device__ float g_wt[64 * 9 * 512 * 8];            // [c8][tap][o][perm-k]  (tf32)
__device__ float g_xmod[16 * 64 * 68 * 68 * 8];     // [b][c8][h2][w2][perm-k] padded, modulated (tf32)

// k-permutation: stored position p holds k = (p>>1) + ((p&1)<<2)
// (so positions 2t,2t+1 hold the mma pair k=t, k=t+4)
__device__ __forceinline__ int kinv(int p) { return (p >> 1) + ((p & 1) << 2); }

__device__ __forceinline__ float f2tf32(float f) {
    unsigned r;
    asm("cvt.rna.tf32.f32 %0, %1;" : "=r"(r) : "f"(f));
    return __uint_as_float(r);
}

__device__ __forceinline__ void mma_tf32(float d[4],
                                         float a0, float a1, float a2, float a3,
                                         float b0, float b1) {
    asm volatile(
        "mma.sync.aligned.m16n8k8.row.col.f32.tf32.tf32.f32 "
        "{%0,%1,%2,%3}, {%4,%5,%6,%7}, {%8,%9}, {%0,%1,%2,%3};"
        : "+f"(d[0]), "+f"(d[1]), "+f"(d[2]), "+f"(d[3])
        : "r"(__float_as_uint(a0)), "r"(__float_as_uint(a1)),
          "r"(__float_as_uint(a2)), "r"(__float_as_uint(a3)),
          "r"(__float_as_uint(b0)), "r"(__float_as_uint(b1)));
}

__device__ __forceinline__ float lrelu2(float v) {
    return (v > 0.0f ? v : 0.2f * v) * SQRT2F;
}

__device__ __forceinline__ unsigned smem_u32(const void* p) {
    return (unsigned)__cvta_generic_to_shared(p);
}
__device__ __forceinline__ void cp16(unsigned dst, const void* src) {
    asm volatile("cp.async.cg.shared.global [%0], [%1], 16;\n" :: "r"(dst), "l"(src));
}

// ---------------- small kernels (fp32 exact) ----------------
__global__ void style_kernel(const float* __restrict__ latent,
                             const float* __restrict__ aw,
                             const float* __restrict__ ab) {
    int b = blockIdx.x;
    int tid = threadIdx.x, lane = tid & 31, warp = tid >> 5;
    __shared__ float lat[512];
    lat[tid] = latent[b * 512 + tid];
    __syncthreads();
    const float wmul = rsqrtf(512.0f);
    for (int n = 0; n < 32; n++) {
        int i = warp * 32 + n;
        const float* wr = aw + (size_t)i * 512;
        float p = 0.0f;
        #pragma unroll 4
        for (int k = lane; k < 512; k += 32) p += wr[k] * lat[k];
        #pragma unroll
        for (int off = 16; off; off >>= 1) p += __shfl_xor_sync(0xFFFFFFFFu, p, off);
        if (lane == 0) g_style[b * 512 + i] = lrelu2(p * wmul + ab[i]);
    }
}

__global__ void wsq_kernel(const float* __restrict__ cw) {
    int o = blockIdx.x, i = threadIdx.x;
    const float* p = cw + (size_t)o * 4608 + (size_t)i * 9;
    float s = 0.0f;
    #pragma unroll
    for (int t = 0; t < 9; t++) s += p[t] * p[t];
    g_wsq[o * 512 + i] = s;
}

__global__ void demod_kernel() {
    int b = blockIdx.x;
    int tid = threadIdx.x, lane = tid & 31, warp = tid >> 5;
    __shared__ float s2[512];
    float st = g_style[b * 512 + tid];
    s2[tid] = st * st;
    __syncthreads();
    for (int n = 0; n < 32; n++) {
        int o = warp * 32 + n;
        const float* wr = g_wsq + (size_t)o * 512;
        float p = 0.0f;
        #pragma unroll 4
        for (int k = lane; k < 512; k += 32) p += wr[k] * s2[k];
        #pragma unroll
        for (int off = 16; off; off >>= 1) p += __shfl_xor_sync(0xFFFFFFFFu, p, off);
        if (lane == 0) g_demod[b * 512 + o] = rsqrtf(p + 1e-8f);
    }
}

// ---------------- preprocess: weights -> [c8][tap][o][perm-k] (tf32) ----------------
__global__ void wt_kernel(const float* __restrict__ cw) {
    int c8 = blockIdx.x, tap = blockIdx.y, o = threadIdx.x;
    float* dst = g_wt + (((size_t)c8 * 9 + tap) * 512 + o) * 8;
    const float* src = cw + (size_t)o * 4608 + (size_t)c8 * 8 * 9 + tap;
    #pragma unroll
    for (int p = 0; p < 8; p++) dst[p] = f2tf32(src[kinv(p) * 9]);
}

// ---------------- preprocess: modulated + padded input -> [b][c8][68][68][perm-k] ----------------
__global__ void xmod_kernel(const float* __restrict__ x,
                            const float* __restrict__ noise,
                            const float* __restrict__ nw_p) {
    const int c8 = blockIdx.x, b = blockIdx.y;
    const int tid = threadIdx.x;
    __shared__ float xs[8][64];
    __shared__ float ns[64];
    __shared__ float sst[8];  // style per stored position p
    const float nw = *nw_p;
    if (tid < 8) sst[tid] = g_style[b * 512 + c8 * 8 + kinv(tid)];

    const float* xb  = x + ((size_t)b * 512 + c8 * 8) * 4096;
    const float* nzb = noise + (size_t)b * 4096;
    float* outb = g_xmod + ((size_t)b * 64 + c8) * (68 * 68 * 8);

    for (int h2 = 0; h2 < 68; h2++) {
        const bool hin = (h2 >= 1) && (h2 <= 64);
        if (hin) {
            int h = h2 - 1;
            // load 8 channel rows (512 elems) + noise row, coalesced
            #pragma unroll
            for (int j = tid; j < 512; j += 256) {
                int k = j >> 6, w = j & 63;
                xs[k][w] = xb[(size_t)k * 4096 + h * 64 + w];
            }
            if (tid < 64) ns[tid] = nzb[h * 64 + tid];
        }
        __syncthreads();
        float* orow = outb + (size_t)h2 * 68 * 8;
        #pragma unroll
        for (int j = tid; j < 544; j += 256) {
            int w2 = j >> 3, p = j & 7;
            float v = 0.0f;
            if (hin && w2 >= 1 && w2 <= 64) {
                int w = w2 - 1;
                v = f2tf32((xs[kinv(p)][w] + nw * ns[w]) * sst[p]);
            }
            orow[j] = v;
        }
        __syncthreads();
    }
}

// ---------------- main conv: implicit GEMM, tf32 mma.sync, cp.async 2-stage ----------------
// CTA: 128 cout x 128 pixels (2 rows). 8 warps (2m x 4n), warp tile 64x32.
// Stage layout (floats): Ws [9][128][8] = 9216, then Xs [4][68][8] = 2176. Stage = 11392.
#define STAGEF 11392
#define XS_OFF 9216

__global__ __launch_bounds__(256, 2)
void conv_kernel(const float* __restrict__ bias, float* __restrict__ out) {
    extern __shared__ float smem[];

    const int b  = blockIdx.z;
    const int o0 = blockIdx.y * 128;
    const int p0 = blockIdx.x * 128;
    const int h0 = p0 >> 6;                    // first of 2 output rows (== first padded row)
    const int tid = threadIdx.x;
    const int lane = tid & 31, warp = tid >> 5;
    const int wm = (warp >> 2) * 64;
    const int wn = (warp & 3) * 32;
    const int g = lane >> 2, t = lane & 3;

    const float* xsrc_base = g_xmod + ((size_t)b * 64) * (68 * 68 * 8) + (size_t)h0 * 68 * 8;

    float d[4][4][4];
    #pragma unroll
    for (int mi = 0; mi < 4; mi++)
        #pragma unroll
        for (int nf = 0; nf < 4; nf++)
            #pragma unroll
            for (int j = 0; j < 4; j++) d[mi][nf][j] = 0.0f;

    // ---- fill stage s with chunk c0 (pure 16B async copies) ----
    auto fill = [&](int c0, int s) {
        float* stage = smem + s * STAGEF;
        // Ws: 9 taps x 1024 floats (contiguous per tap both sides) = 2304 float4
        #pragma unroll
        for (int r = 0; r < 9; r++) {
            int i = tid + r * 256;
            int tap = i >> 8, w4 = i & 255;
            const float* src = g_wt + (((size_t)c0 * 9 + tap) * 512 + o0) * 8 + w4 * 4;
            cp16(smem_u32(stage + tap * 1024 + w4 * 4), src);
        }
        // Xs: 4 rows x 68 x 8 = 2176 floats, fully contiguous both sides = 544 float4
        const float* xsrc = xsrc_base + (size_t)c0 * (68 * 68 * 8);
        cp16(smem_u32(stage + XS_OFF + tid * 4), xsrc + tid * 4);
        cp16(smem_u32(stage + XS_OFF + (tid + 256) * 4), xsrc + (tid + 256) * 4);
        if (tid < 32) cp16(smem_u32(stage + XS_OFF + (tid + 512) * 4), xsrc + (tid + 512) * 4);
    };

    fill(0, 0);
    asm volatile("cp.async.commit_group;\n");

    for (int c = 0; c < 64; c++) {
        if (c + 1 < 64) fill(c + 1, (c + 1) & 1);
        asm volatile("cp.async.commit_group;\n");
        asm volatile("cp.async.wait_group 1;\n");
        __syncthreads();

        const float* sW = smem + (c & 1) * STAGEF;
        const float* sX = sW + XS_OFF;

        #pragma unroll
        for (int tap = 0; tap < 9; tap++) {
            const int dy = tap / 3, dx = tap - dy * 3;
            float2 A0[4], A1[4];
            #pragma unroll
            for (int mi = 0; mi < 4; mi++) {
                int row = wm + mi * 16 + g;
                A0[mi] = *reinterpret_cast<const float2*>(sW + tap * 1024 + row * 8 + 2 * t);
                A1[mi] = *reinterpret_cast<const float2*>(sW + tap * 1024 + (row + 8) * 8 + 2 * t);
            }
            #pragma unroll
            for (int nf = 0; nf < 4; nf++) {
                int nb2 = wn + nf * 8;
                int row = (nb2 >> 6) + dy;
                int col = (nb2 & 63) + g + dx;
                float2 Bv = *reinterpret_cast<const float2*>(sX + (row * 68 + col) * 8 + 2 * t);
                #pragma unroll
                for (int mi = 0; mi < 4; mi++)
                    mma_tf32(d[mi][nf], A0[mi].x, A1[mi].x, A0[mi].y, A1[mi].y, Bv.x, Bv.y);
            }
        }
        __syncthreads();
    }

    // ---- epilogue: demod, bias, leaky-relu*sqrt2 ----
    const float* dm = g_demod + b * 512;
    #pragma unroll
    for (int mi = 0; mi < 4; mi++) {
        int o = o0 + wm + mi * 16 + g;
        float dem0 = dm[o],     bv0 = bias[o];
        float dem1 = dm[o + 8], bv1 = bias[o + 8];
        float* r0 = out + ((size_t)b * 512 + o) * 4096 + p0 + wn;
        float* r1 = r0 + (size_t)8 * 4096;
        #pragma unroll
        for (int nf = 0; nf < 4; nf++) {
            int col = nf * 8 + 2 * t;
            float2 v0, v1;
            v0.x = lrelu2(d[mi][nf][0] * dem0 + bv0);
            v0.y = lrelu2(d[mi][nf][1] * dem0 + bv0);
            v1.x = lrelu2(d[mi][nf][2] * dem1 + bv1);
            v1.y = lrelu2(d[mi][nf][3] * dem1 + bv1);
            *reinterpret_cast<float2*>(r0 + col) = v0;
            *reinterpret_cast<float2*>(r1 + col) = v1;
        }
    }
}

// ---------------- launch ----------------
extern "C" void kernel_launch(void* const* d_in, const int* in_sizes, int n_in,
                              void* d_out, int out_size) {
    const float* x      = (const float*)d_in[0];
    const float* latent = (const float*)d_in[1];
    const float* noise  = (const float*)d_in[2];
    const float* aw     = (const float*)d_in[3];
    const float* ab     = (const float*)d_in[4];
    const float* cw     = (const float*)d_in[5];
    const float* nw     = (const float*)d_in[6];
    const float* bias   = (const float*)d_in[7];
    float* out = (float*)d_out;

    cudaFuncSetAttribute(conv_kernel, cudaFuncAttributeMaxDynamicSharedMemorySize,
                         2 * STAGEF * (int)sizeof(float));

    style_kernel<<<16, 512>>>(latent, aw, ab);
    wsq_kernel<<<512, 512>>>(cw);
    demod_kernel<<<16, 512>>>();
    wt_kernel<<<dim3(64, 9), 512>>>(cw);
    xmod_kernel<<<dim3(64, 16), 256>>>(x, noise, nw);
    conv_kernel<<<dim3(32, 4, 16), 256, 2 * STAGEF * sizeof(float)>>>(bias, out);
}

// round 4
// speedup vs baseline: 2.2160x; 1.0003x over previous
#include <cuda_runtime.h>
#include <cuda_bf16.h>
#include <cstdint>

#define SQRT2F 1.41421356237309515f

// ---------------- scratch (allocation-free: __device__ globals) ----------------
__device__ float g_style[16 * 512];                 // style[b,i]
__device__ float g_demod[16 * 512];                 // demod[b,o]
__device__ float g_wsq[512 * 512];                  // sum_tap w[o,i,tap]^2
__device__ float g_wt[64 * 9 * 512 * 8];            // [c8][tap][o][perm-k]  (tf32)
__device__ float g_xmod[16 * 64 * 68 * 68 * 8];     // [b][c8][h2][w2][perm-k] padded, modulated (tf32)

// k-permutation: stored position p holds k = (p>>1) + ((p&1)<<2)
// (so positions 2t,2t+1 hold the mma pair k=t, k=t+4)
__device__ __forceinline__ int kinv(int p) { return (p >> 1) + ((p & 1) << 2); }

__device__ __forceinline__ float f2tf32(float f) {
    unsigned r;
    asm("cvt.rna.tf32.f32 %0, %1;" : "=r"(r) : "f"(f));
    return __uint_as_float(r);
}

__device__ __forceinline__ void mma_tf32(float d[4],
                                         float a0, float a1, float a2, float a3,
                                         float b0, float b1) {
    asm volatile(
        "mma.sync.aligned.m16n8k8.row.col.f32.tf32.tf32.f32 "
        "{%0,%1,%2,%3}, {%4,%5,%6,%7}, {%8,%9}, {%0,%1,%2,%3};"
        : "+f"(d[0]), "+f"(d[1]), "+f"(d[2]), "+f"(d[3])
        : "r"(__float_as_uint(a0)), "r"(__float_as_uint(a1)),
          "r"(__float_as_uint(a2)), "r"(__float_as_uint(a3)),
          "r"(__float_as_uint(b0)), "r"(__float_as_uint(b1)));
}

__device__ __forceinline__ float lrelu2(float v) {
    return (v > 0.0f ? v : 0.2f * v) * SQRT2F;
}

__device__ __forceinline__ unsigned smem_u32(const void* p) {
    return (unsigned)__cvta_generic_to_shared(p);
}
__device__ __forceinline__ void cp16(unsigned dst, const void* src) {
    asm volatile("cp.async.cg.shared.global [%0], [%1], 16;\n" :: "r"(dst), "l"(src));
}

// ---------------- small kernels (fp32 exact) ----------------
__global__ void style_kernel(const float* __restrict__ latent,
                             const float* __restrict__ aw,
                             const float* __restrict__ ab) {
    int b = blockIdx.x;
    int tid = threadIdx.x, lane = tid & 31, warp = tid >> 5;
    __shared__ float lat[512];
    lat[tid] = latent[b * 512 + tid];
    __syncthreads();
    const float wmul = rsqrtf(512.0f);
    for (int n = 0; n < 32; n++) {
        int i = warp * 32 + n;
        const float* wr = aw + (size_t)i * 512;
        float p = 0.0f;
        #pragma unroll 4
        for (int k = lane; k < 512; k += 32) p += wr[k] * lat[k];
        #pragma unroll
        for (int off = 16; off; off >>= 1) p += __shfl_xor_sync(0xFFFFFFFFu, p, off);
        if (lane == 0) g_style[b * 512 + i] = lrelu2(p * wmul + ab[i]);
    }
}

__global__ void wsq_kernel(const float* __restrict__ cw) {
    int o = blockIdx.x, i = threadIdx.x;
    const float* p = cw + (size_t)o * 4608 + (size_t)i * 9;
    float s = 0.0f;
    #pragma unroll
    for (int t = 0; t < 9; t++) s += p[t] * p[t];
    g_wsq[o * 512 + i] = s;
}

__global__ void demod_kernel() {
    int b = blockIdx.x;
    int tid = threadIdx.x, lane = tid & 31, warp = tid >> 5;
    __shared__ float s2[512];
    float st = g_style[b * 512 + tid];
    s2[tid] = st * st;
    __syncthreads();
    for (int n = 0; n < 32; n++) {
        int o = warp * 32 + n;
        const float* wr = g_wsq + (size_t)o * 512;
        float p = 0.0f;
        #pragma unroll 4
        for (int k = lane; k < 512; k += 32) p += wr[k] * s2[k];
        #pragma unroll
        for (int off = 16; off; off >>= 1) p += __shfl_xor_sync(0xFFFFFFFFu, p, off);
        if (lane == 0) g_demod[b * 512 + o] = rsqrtf(p + 1e-8f);
    }
}

// ---------------- preprocess: weights -> [c8][tap][o][perm-k] (tf32) ----------------
__global__ void wt_kernel(const float* __restrict__ cw) {
    int c8 = blockIdx.x, tap = blockIdx.y, o = threadIdx.x;
    float* dst = g_wt + (((size_t)c8 * 9 + tap) * 512 + o) * 8;
    const float* src = cw + (size_t)o * 4608 + (size_t)c8 * 8 * 9 + tap;
    #pragma unroll
    for (int p = 0; p < 8; p++) dst[p] = f2tf32(src[kinv(p) * 9]);
}

// ---------------- preprocess: modulated + padded input -> [b][c8][68][68][perm-k] ----------------
__global__ void xmod_kernel(const float* __restrict__ x,
                            const float* __restrict__ noise,
                            const float* __restrict__ nw_p) {
    const int c8 = blockIdx.x, b = blockIdx.y;
    const int tid = threadIdx.x;
    __shared__ float xs[8][64];
    __shared__ float ns[64];
    __shared__ float sst[8];  // style per stored position p
    const float nw = *nw_p;
    if (tid < 8) sst[tid] = g_style[b * 512 + c8 * 8 + kinv(tid)];

    const float* xb  = x + ((size_t)b * 512 + c8 * 8) * 4096;
    const float* nzb = noise + (size_t)b * 4096;
    float* outb = g_xmod + ((size_t)b * 64 + c8) * (68 * 68 * 8);

    for (int h2 = 0; h2 < 68; h2++) {
        const bool hin = (h2 >= 1) && (h2 <= 64);
        if (hin) {
            int h = h2 - 1;
            // load 8 channel rows (512 elems) + noise row, coalesced
            #pragma unroll
            for (int j = tid; j < 512; j += 256) {
                int k = j >> 6, w = j & 63;
                xs[k][w] = xb[(size_t)k * 4096 + h * 64 + w];
            }
            if (tid < 64) ns[tid] = nzb[h * 64 + tid];
        }
        __syncthreads();
        float* orow = outb + (size_t)h2 * 68 * 8;
        #pragma unroll
        for (int j = tid; j < 544; j += 256) {
            int w2 = j >> 3, p = j & 7;
            float v = 0.0f;
            if (hin && w2 >= 1 && w2 <= 64) {
                int w = w2 - 1;
                v = f2tf32((xs[kinv(p)][w] + nw * ns[w]) * sst[p]);
            }
            orow[j] = v;
        }
        __syncthreads();
    }
}

// ---------------- main conv: implicit GEMM, tf32 mma.sync, cp.async 2-stage ----------------
// CTA: 128 cout x 128 pixels (2 rows). 8 warps (2m x 4n), warp tile 64x32.
// Stage layout (floats): Ws [9][128][8] = 9216, then Xs [4][68][8] = 2176. Stage = 11392.
#define STAGEF 11392
#define XS_OFF 9216

__global__ __launch_bounds__(256, 2)
void conv_kernel(const float* __restrict__ bias, float* __restrict__ out) {
    extern __shared__ float smem[];

    const int b  = blockIdx.z;
    const int o0 = blockIdx.y * 128;
    const int p0 = blockIdx.x * 128;
    const int h0 = p0 >> 6;                    // first of 2 output rows (== first padded row)
    const int tid = threadIdx.x;
    const int lane = tid & 31, warp = tid >> 5;
    const int wm = (warp >> 2) * 64;
    const int wn = (warp & 3) * 32;
    const int g = lane >> 2, t = lane & 3;

    const float* xsrc_base = g_xmod + ((size_t)b * 64) * (68 * 68 * 8) + (size_t)h0 * 68 * 8;

    float d[4][4][4];
    #pragma unroll
    for (int mi = 0; mi < 4; mi++)
        #pragma unroll
        for (int nf = 0; nf < 4; nf++)
            #pragma unroll
            for (int j = 0; j < 4; j++) d[mi][nf][j] = 0.0f;

    // ---- fill stage s with chunk c0 (pure 16B async copies) ----
    auto fill = [&](int c0, int s) {
        float* stage = smem + s * STAGEF;
        // Ws: 9 taps x 1024 floats (contiguous per tap both sides) = 2304 float4
        #pragma unroll
        for (int r = 0; r < 9; r++) {
            int i = tid + r * 256;
            int tap = i >> 8, w4 = i & 255;
            const float* src = g_wt + (((size_t)c0 * 9 + tap) * 512 + o0) * 8 + w4 * 4;
            cp16(smem_u32(stage + tap * 1024 + w4 * 4), src);
        }
        // Xs: 4 rows x 68 x 8 = 2176 floats, fully contiguous both sides = 544 float4
        const float* xsrc = xsrc_base + (size_t)c0 * (68 * 68 * 8);
        cp16(smem_u32(stage + XS_OFF + tid * 4), xsrc + tid * 4);
        cp16(smem_u32(stage + XS_OFF + (tid + 256) * 4), xsrc + (tid + 256) * 4);
        if (tid < 32) cp16(smem_u32(stage + XS_OFF + (tid + 512) * 4), xsrc + (tid + 512) * 4);
    };

    fill(0, 0);
    asm volatile("cp.async.commit_group;\n");

    for (int c = 0; c < 64; c++) {
        if (c + 1 < 64) fill(c + 1, (c + 1) & 1);
        asm volatile("cp.async.commit_group;\n");
        asm volatile("cp.async.wait_group 1;\n");
        __syncthreads();

        const float* sW = smem + (c & 1) * STAGEF;
        const float* sX = sW + XS_OFF;

        #pragma unroll
        for (int tap = 0; tap < 9; tap++) {
            const int dy = tap / 3, dx = tap - dy * 3;
            float2 A0[4], A1[4];
            #pragma unroll
            for (int mi = 0; mi < 4; mi++) {
                int row = wm + mi * 16 + g;
                A0[mi] = *reinterpret_cast<const float2*>(sW + tap * 1024 + row * 8 + 2 * t);
                A1[mi] = *reinterpret_cast<const float2*>(sW + tap * 1024 + (row + 8) * 8 + 2 * t);
            }
            #pragma unroll
            for (int nf = 0; nf < 4; nf++) {
                int nb2 = wn + nf * 8;
                int row = (nb2 >> 6) + dy;
                int col = (nb2 & 63) + g + dx;
                float2 Bv = *reinterpret_cast<const float2*>(sX + (row * 68 + col) * 8 + 2 * t);
                #pragma unroll
                for (int mi = 0; mi < 4; mi++)
                    mma_tf32(d[mi][nf], A0[mi].x, A1[mi].x, A0[mi].y, A1[mi].y, Bv.x, Bv.y);
            }
        }
        __syncthreads();
    }

    // ---- epilogue: demod, bias, leaky-relu*sqrt2 ----
    const float* dm = g_demod + b * 512;
    #pragma unroll
    for (int mi = 0; mi < 4; mi++) {
        int o = o0 + wm + mi * 16 + g;
        float dem0 = dm[o],     bv0 = bias[o];
        float dem1 = dm[o + 8], bv1 = bias[o + 8];
        float* r0 = out + ((size_t)b * 512 + o) * 4096 + p0 + wn;
        float* r1 = r0 + (size_t)8 * 4096;
        #pragma unroll
        for (int nf = 0; nf < 4; nf++) {
            int col = nf * 8 + 2 * t;
            float2 v0, v1;
            v0.x = lrelu2(d[mi][nf][0] * dem0 + bv0);
            v0.y = lrelu2(d[mi][nf][1] * dem0 + bv0);
            v1.x = lrelu2(d[mi][nf][2] * dem1 + bv1);
            v1.y = lrelu2(d[mi][nf][3] * dem1 + bv1);
            *reinterpret_cast<float2*>(r0 + col) = v0;
            *reinterpret_cast<float2*>(r1 + col) = v1;
        }
    }
}

// ---------------- launch ----------------
extern "C" void kernel_launch(void* const* d_in, const int* in_sizes, int n_in,
                              void* d_out, int out_size) {
    const float* x      = (const float*)d_in[0];
    const float* latent = (const float*)d_in[1];
    const float* noise  = (const float*)d_in[2];
    const float* aw     = (const float*)d_in[3];
    const float* ab     = (const float*)d_in[4];
    const float* cw     = (const float*)d_in[5];
    const float* nw     = (const float*)d_in[6];
    const float* bias   = (const float*)d_in[7];
    float* out = (float*)d_out;

    cudaFuncSetAttribute(conv_kernel, cudaFuncAttributeMaxDynamicSharedMemorySize,
                         2 * STAGEF * (int)sizeof(float));

    style_kernel<<<16, 512>>>(latent, aw, ab);
    wsq_kernel<<<512, 512>>>(cw);
    demod_kernel<<<16, 512>>>();
    wt_kernel<<<dim3(64, 9), 512>>>(cw);
    xmod_kernel<<<dim3(64, 16), 256>>>(x, noise, nw);
    conv_kernel<<<dim3(32, 4, 16), 256, 2 * STAGEF * sizeof(float)>>>(bias, out);
}